// round 5
// baseline (speedup 1.0000x reference)
#include <cuda_runtime.h>
#include <cuda_fp16.h>
#include <cstdint>

#define NODES 100000
#define EMAX  1600000
#define F0 128
#define F1 64
#define F2 32
#define NB_SCAN 196
#define NPAD (NB_SCAN*512)

// ---- scratch (static device globals: allocation-free) ----
__device__ int    d_degi[NODES];
__device__ int    d_loc[NPAD];
__device__ int    d_part[NB_SCAN];
__device__ int    d_off[NODES + 1];
__device__ int    d_pos[NODES];
__device__ int    d_csr[EMAX];
__device__ float  d_dinv[NODES];
__device__ __half d_g1[(size_t)NODES * F1];   // x@W1 (unscaled), fp16 messages
__device__ float  d_h1[(size_t)NODES * F1];   // relu-normalized layer-1 output (fp32)
__device__ __half d_g2[(size_t)NODES * F2];   // (h1@W2)*dinv, fp16 messages

struct SideStream {
    cudaStream_t s;
    cudaEvent_t fork, join;
    SideStream() {
        cudaStreamCreateWithFlags(&s, cudaStreamNonBlocking);
        cudaEventCreateWithFlags(&fork, cudaEventDisableTiming);
        cudaEventCreateWithFlags(&join, cudaEventDisableTiming);
    }
};
static SideStream g_ss;

// ================= degree histogram =================
__global__ void k_zero(int n) {
    int i = blockIdx.x * blockDim.x + threadIdx.x;
    if (i < n) d_degi[i] = 0;
}

__global__ void k_count(const int* __restrict__ dst, int e) {
    int i = blockIdx.x * blockDim.x + threadIdx.x;
    if (i < e) atomicAdd(&d_degi[dst[i]], 1);
}

// ================= scan pass 1 =================
__global__ void k_scan1(int n) {
    __shared__ int s[512];
    int i = blockIdx.x * 512 + threadIdx.x;
    int v = (i < n) ? d_degi[i] : 0;
    s[threadIdx.x] = v;
    __syncthreads();
#pragma unroll
    for (int off = 1; off < 512; off <<= 1) {
        int t = (threadIdx.x >= off) ? s[threadIdx.x - off] : 0;
        __syncthreads();
        s[threadIdx.x] += t;
        __syncthreads();
    }
    d_loc[i] = s[threadIdx.x] - v;
    if (threadIdx.x == 511) d_part[blockIdx.x] = s[511];
}

// ================= scan pass 2 (fused partial-rescan) =================
__global__ void k_scan2f(int n, int nb, int e) {
    __shared__ int s[256];
    __shared__ int sOrig[256];
    int t = threadIdx.x;
    if (t < 256) {
        int v = (t < nb) ? d_part[t] : 0;
        s[t] = v;
        sOrig[t] = v;
    }
    __syncthreads();
#pragma unroll
    for (int off = 1; off < 256; off <<= 1) {
        int tv = 0;
        if (t < 256 && t >= off) tv = s[t - off];
        __syncthreads();
        if (t < 256) s[t] += tv;
        __syncthreads();
    }
    int pref = s[blockIdx.x] - sOrig[blockIdx.x];
    int i = blockIdx.x * 512 + t;
    if (i < n) {
        int o = d_loc[i] + pref;
        d_off[i] = o;
        d_pos[i] = o;
        d_dinv[i] = rsqrtf(1.0f + (float)d_degi[i]);
    }
    if (blockIdx.x == 0 && t == 0) d_off[n] = e;
}

// ================= CSR fill =================
__global__ void k_fill(const int* __restrict__ src, const int* __restrict__ dst, int e) {
    int i = blockIdx.x * blockDim.x + threadIdx.x;
    if (i < e) {
        int d = dst[i];
        int p = atomicAdd(&d_pos[d], 1);
        d_csr[p] = src[i];
    }
}

// ================= GEMM1: g1 = x @ W1 (unscaled, fp16 out) =================
__global__ void k_gemm1(const float* __restrict__ x, const float* __restrict__ W, int n) {
    __shared__ float4 xs4[32 * 33];
    __shared__ float  ws[32][68];
    int tid = threadIdx.x;
    int tx = tid & 15, ty = tid >> 4;
    int nodeBase = blockIdx.x * 128;
    float acc[8][4] = {};

    for (int kc = 0; kc < F0; kc += 32) {
#pragma unroll
        for (int i = 0; i < 4; ++i) {
            int flat = i * 256 + tid;
            int row = flat >> 3;
            int c4  = flat & 7;
            int node = nodeBase + row;
            float4 v = make_float4(0.f, 0.f, 0.f, 0.f);
            if (node < n) v = __ldg((const float4*)(x + (size_t)node * F0 + kc + 4 * c4));
            int g = row >> 2, el = row & 3;
            const float vv[4] = {v.x, v.y, v.z, v.w};
#pragma unroll
            for (int j = 0; j < 4; ++j) {
                int k = 4 * c4 + j;
                float* p = (float*)&xs4[k * 33 + (g ^ ((k >> 2) & 7))];
                p[el] = vv[j];
            }
        }
#pragma unroll
        for (int i = 0; i < 2; ++i) {
            int flat = i * 256 + tid;
            int k = flat >> 4;
            int c4 = flat & 15;
            float4 w = __ldg((const float4*)(W + (size_t)(kc + k) * F1 + 4 * c4));
            *(float4*)&ws[k][4 * c4] = w;
        }
        __syncthreads();
#pragma unroll
        for (int k = 0; k < 32; ++k) {
            int swz = (k >> 2) & 7;
            float4 A0 = xs4[k * 33 + ((2 * ty) ^ swz)];
            float4 A1 = xs4[k * 33 + ((2 * ty + 1) ^ swz)];
            float4 B  = *(const float4*)&ws[k][4 * tx];
            float a[8] = {A0.x, A0.y, A0.z, A0.w, A1.x, A1.y, A1.z, A1.w};
            float b[4] = {B.x, B.y, B.z, B.w};
#pragma unroll
            for (int m = 0; m < 8; ++m)
#pragma unroll
                for (int q = 0; q < 4; ++q)
                    acc[m][q] += a[m] * b[q];
        }
        __syncthreads();
    }

#pragma unroll
    for (int m = 0; m < 8; ++m) {
        int node = nodeBase + 8 * ty + m;
        if (node < n) {
            __half2 p0 = __floats2half2_rn(acc[m][0], acc[m][1]);
            __half2 p1 = __floats2half2_rn(acc[m][2], acc[m][3]);
            uint2 u;
            u.x = *(unsigned*)&p0;
            u.y = *(unsigned*)&p1;
            ((uint2*)d_g1)[(size_t)node * 16 + tx] = u;  // cols 4tx..4tx+3
        }
    }
}

// ================= Gather layer1 =================
// h1[d] = relu(dinv[d]*(sum_s dinv[s]*g1[s] + dinv[d]*g1[d]) + b1)
// 8 lanes/node, each lane: 8 halfs (uint4) -> 8 fp32 accumulators.
__device__ __forceinline__ void h8_fma(float* acc, uint4 u, float w) {
    __half2 h0 = *(__half2*)&u.x;
    __half2 h1 = *(__half2*)&u.y;
    __half2 h2 = *(__half2*)&u.z;
    __half2 h3 = *(__half2*)&u.w;
    float2 f0 = __half22float2(h0), f1 = __half22float2(h1);
    float2 f2 = __half22float2(h2), f3 = __half22float2(h3);
    acc[0] = fmaf(f0.x, w, acc[0]); acc[1] = fmaf(f0.y, w, acc[1]);
    acc[2] = fmaf(f1.x, w, acc[2]); acc[3] = fmaf(f1.y, w, acc[3]);
    acc[4] = fmaf(f2.x, w, acc[4]); acc[5] = fmaf(f2.y, w, acc[5]);
    acc[6] = fmaf(f3.x, w, acc[6]); acc[7] = fmaf(f3.y, w, acc[7]);
}

__global__ void k_gather1(const float* __restrict__ b1, int n) {
    int grp = threadIdx.x >> 3, lane = threadIdx.x & 7;
    int node = blockIdx.x * 32 + grp;
    if (node >= n) return;
    const uint4* g1 = (const uint4*)d_g1;  // 8 uint4 per row
    float dv = d_dinv[node];
    float acc[8] = {};
    h8_fma(acc, __ldg(&g1[(size_t)node * 8 + lane]), dv);  // self loop
    int beg = d_off[node], end = d_off[node + 1];
    int j = beg;
    for (; j + 4 <= end; j += 4) {
        int s0 = __ldg(&d_csr[j + 0]);
        int s1 = __ldg(&d_csr[j + 1]);
        int s2 = __ldg(&d_csr[j + 2]);
        int s3 = __ldg(&d_csr[j + 3]);
        float w0 = __ldg(&d_dinv[s0]);
        float w1 = __ldg(&d_dinv[s1]);
        float w2 = __ldg(&d_dinv[s2]);
        float w3 = __ldg(&d_dinv[s3]);
        uint4 v0 = __ldg(&g1[(size_t)s0 * 8 + lane]);
        uint4 v1 = __ldg(&g1[(size_t)s1 * 8 + lane]);
        uint4 v2 = __ldg(&g1[(size_t)s2 * 8 + lane]);
        uint4 v3 = __ldg(&g1[(size_t)s3 * 8 + lane]);
        h8_fma(acc, v0, w0);
        h8_fma(acc, v1, w1);
        h8_fma(acc, v2, w2);
        h8_fma(acc, v3, w3);
    }
    for (; j < end; ++j) {
        int s = __ldg(&d_csr[j]);
        float w = __ldg(&d_dinv[s]);
        h8_fma(acc, __ldg(&g1[(size_t)s * 8 + lane]), w);
    }
    float4 ba = __ldg(&((const float4*)b1)[2 * lane + 0]);
    float4 bbq = __ldg(&((const float4*)b1)[2 * lane + 1]);
    float4 o0, o1;
    o0.x = fmaxf(fmaf(acc[0], dv, ba.x), 0.f);
    o0.y = fmaxf(fmaf(acc[1], dv, ba.y), 0.f);
    o0.z = fmaxf(fmaf(acc[2], dv, ba.z), 0.f);
    o0.w = fmaxf(fmaf(acc[3], dv, ba.w), 0.f);
    o1.x = fmaxf(fmaf(acc[4], dv, bbq.x), 0.f);
    o1.y = fmaxf(fmaf(acc[5], dv, bbq.y), 0.f);
    o1.z = fmaxf(fmaf(acc[6], dv, bbq.z), 0.f);
    o1.w = fmaxf(fmaf(acc[7], dv, bbq.w), 0.f);
    float4* h1p = (float4*)(d_h1 + (size_t)node * F1 + lane * 8);
    h1p[0] = o0;
    h1p[1] = o1;
}

// ================= GEMM2: g2 = (h1 @ W2) * dinv (fp16 out) =================
__global__ void k_gemm2(const float* __restrict__ W2, int n) {
    __shared__ float4 xs4[64 * 33];
    __shared__ float  ws[64][36];
    int tid = threadIdx.x;
    int tx = tid & 15, ty = tid >> 4;
    int nodeBase = blockIdx.x * 128;
    float acc[8][2] = {};

#pragma unroll
    for (int i = 0; i < 8; ++i) {
        int flat = i * 256 + tid;
        int row = flat >> 4;
        int c4  = flat & 15;
        int node = nodeBase + row;
        float4 v = make_float4(0.f, 0.f, 0.f, 0.f);
        if (node < n) v = __ldg((const float4*)(d_h1 + (size_t)node * F1 + 4 * c4));
        int g = row >> 2, el = row & 3;
        const float vv[4] = {v.x, v.y, v.z, v.w};
#pragma unroll
        for (int j = 0; j < 4; ++j) {
            int k = 4 * c4 + j;
            float* p = (float*)&xs4[k * 33 + (g ^ ((k >> 2) & 7))];
            p[el] = vv[j];
        }
    }
#pragma unroll
    for (int i = 0; i < 2; ++i) {
        int flat = i * 256 + tid;
        int k = flat >> 3;
        int c4 = flat & 7;
        float4 w = __ldg((const float4*)(W2 + (size_t)k * F2 + 4 * c4));
        *(float4*)&ws[k][4 * c4] = w;
    }
    __syncthreads();

#pragma unroll
    for (int k = 0; k < 64; ++k) {
        int swz = (k >> 2) & 7;
        float4 A0 = xs4[k * 33 + ((2 * ty) ^ swz)];
        float4 A1 = xs4[k * 33 + ((2 * ty + 1) ^ swz)];
        float b0 = ws[k][2 * tx + 0];
        float b1 = ws[k][2 * tx + 1];
        float a[8] = {A0.x, A0.y, A0.z, A0.w, A1.x, A1.y, A1.z, A1.w};
#pragma unroll
        for (int m = 0; m < 8; ++m) {
            acc[m][0] += a[m] * b0;
            acc[m][1] += a[m] * b1;
        }
    }

#pragma unroll
    for (int m = 0; m < 8; ++m) {
        int node = nodeBase + 8 * ty + m;
        if (node < n) {
            float dv = d_dinv[node];
            __half2 p = __floats2half2_rn(acc[m][0] * dv, acc[m][1] * dv);
            ((__half2*)d_g2)[(size_t)node * 16 + tx] = p;  // cols 2tx,2tx+1
        }
    }
}

// ================= Gather layer2: out = (sum g2[s] + g2[d])*dinv + b2 ====
// 8 lanes/node, each lane: 4 halfs (uint2) -> 4 fp32 accumulators.
__device__ __forceinline__ void h4_add(float* acc, uint2 u) {
    __half2 h0 = *(__half2*)&u.x;
    __half2 h1 = *(__half2*)&u.y;
    float2 f0 = __half22float2(h0), f1 = __half22float2(h1);
    acc[0] += f0.x; acc[1] += f0.y; acc[2] += f1.x; acc[3] += f1.y;
}

__global__ void k_gather2(const float* __restrict__ b2, float* __restrict__ out, int n) {
    int grp = threadIdx.x >> 3, lane = threadIdx.x & 7;
    int node = blockIdx.x * 32 + grp;
    if (node >= n) return;
    const uint2* g2 = (const uint2*)d_g2;  // 8 uint2 per row
    float acc[4] = {};
    h4_add(acc, __ldg(&g2[(size_t)node * 8 + lane]));  // self loop (pre-scaled)
    int beg = d_off[node], end = d_off[node + 1];
    int j = beg;
    for (; j + 4 <= end; j += 4) {
        int s0 = __ldg(&d_csr[j + 0]);
        int s1 = __ldg(&d_csr[j + 1]);
        int s2 = __ldg(&d_csr[j + 2]);
        int s3 = __ldg(&d_csr[j + 3]);
        uint2 v0 = __ldg(&g2[(size_t)s0 * 8 + lane]);
        uint2 v1 = __ldg(&g2[(size_t)s1 * 8 + lane]);
        uint2 v2 = __ldg(&g2[(size_t)s2 * 8 + lane]);
        uint2 v3 = __ldg(&g2[(size_t)s3 * 8 + lane]);
        h4_add(acc, v0);
        h4_add(acc, v1);
        h4_add(acc, v2);
        h4_add(acc, v3);
    }
    for (; j < end; ++j) {
        int s = __ldg(&d_csr[j]);
        h4_add(acc, __ldg(&g2[(size_t)s * 8 + lane]));
    }
    float dv = d_dinv[node];
    float4 bb = __ldg(&((const float4*)b2)[lane]);
    float4 o;
    o.x = fmaf(acc[0], dv, bb.x);
    o.y = fmaf(acc[1], dv, bb.y);
    o.z = fmaf(acc[2], dv, bb.z);
    o.w = fmaf(acc[3], dv, bb.w);
    ((float4*)out)[(size_t)node * 8 + lane] = o;
}

extern "C" void kernel_launch(void* const* d_in, const int* in_sizes, int n_in,
                              void* d_out, int out_size) {
    const float* x  = (const float*)d_in[0];
    const int*   ei = (const int*)d_in[1];
    const float* W1 = (const float*)d_in[2];
    const float* b1 = (const float*)d_in[3];
    const float* W2 = (const float*)d_in[4];
    const float* b2 = (const float*)d_in[5];
    float* out = (float*)d_out;

    int n = in_sizes[0] / F0;   // 100000
    int e = in_sizes[1] / 2;    // 1600000
    const int* src = ei;
    const int* dst = ei + e;
    int nb = (n + 511) / 512;   // 196

    // Fork: GEMM1 on side stream (independent of graph structure).
    cudaEventRecord(g_ss.fork, 0);
    cudaStreamWaitEvent(g_ss.s, g_ss.fork, 0);
    k_gemm1<<<(n + 127) / 128, 256, 0, g_ss.s>>>(x, W1, n);

    // CSR build on main stream.
    k_zero<<<(n + 255) / 256, 256>>>(n);
    k_count<<<(e + 255) / 256, 256>>>(dst, e);
    k_scan1<<<nb, 512>>>(n);
    k_scan2f<<<nb, 512>>>(n, nb, e);
    k_fill<<<(e + 255) / 256, 256>>>(src, dst, e);

    cudaEventRecord(g_ss.join, g_ss.s);
    cudaStreamWaitEvent(0, g_ss.join, 0);

    k_gather1<<<(n + 31) / 32, 256>>>(b1, n);
    k_gemm2<<<(n + 127) / 128, 256>>>(W2, n);
    k_gather2<<<(n + 31) / 32, 256>>>(b2, out, n);
}

// round 6
// speedup vs baseline: 1.2116x; 1.2116x over previous
#include <cuda_runtime.h>
#include <cuda_fp16.h>
#include <cstdint>

#define NODES 100000
#define EMAX  1600000
#define F0 128
#define F1 64
#define F2 32
#define NB_SCAN 196
#define NPAD (NB_SCAN*512)

// ---- scratch (static device globals: allocation-free) ----
__device__ int    d_degi[NODES];
__device__ int    d_loc[NPAD];
__device__ int    d_part[NB_SCAN];
__device__ int    d_off[NODES + 1];
__device__ int    d_pos[NODES];
__device__ int    d_csr[EMAX];
__device__ float  d_dinv[NODES];
__device__ __half d_g1[(size_t)NODES * F1];   // x@W1 (UNSCALED), fp16 messages
__device__ float  d_h1[(size_t)NODES * F1];   // relu-normalized layer-1 output (fp32)
__device__ __half d_g2[(size_t)NODES * F2];   // (h1@W2)*dinv, fp16 messages

struct SideStream {
    cudaStream_t s;
    cudaEvent_t fork, join;
    SideStream() {
        cudaStreamCreateWithFlags(&s, cudaStreamNonBlocking);
        cudaEventCreateWithFlags(&fork, cudaEventDisableTiming);
        cudaEventCreateWithFlags(&join, cudaEventDisableTiming);
    }
};
static SideStream g_ss;

// ================= degree histogram =================
__global__ void k_zero(int n) {
    int i = blockIdx.x * blockDim.x + threadIdx.x;
    if (i < n) d_degi[i] = 0;
}

__global__ void k_count(const int* __restrict__ dst, int e) {
    int i = blockIdx.x * blockDim.x + threadIdx.x;
    if (i < e) atomicAdd(&d_degi[dst[i]], 1);
}

// ================= scan pass 1 =================
__global__ void k_scan1(int n) {
    __shared__ int s[512];
    int i = blockIdx.x * 512 + threadIdx.x;
    int v = (i < n) ? d_degi[i] : 0;
    s[threadIdx.x] = v;
    __syncthreads();
#pragma unroll
    for (int off = 1; off < 512; off <<= 1) {
        int t = (threadIdx.x >= off) ? s[threadIdx.x - off] : 0;
        __syncthreads();
        s[threadIdx.x] += t;
        __syncthreads();
    }
    d_loc[i] = s[threadIdx.x] - v;
    if (threadIdx.x == 511) d_part[blockIdx.x] = s[511];
}

// ================= scan pass 2 (fused partial-rescan) =================
__global__ void k_scan2f(int n, int nb, int e) {
    __shared__ int s[256];
    __shared__ int sOrig[256];
    int t = threadIdx.x;
    if (t < 256) {
        int v = (t < nb) ? d_part[t] : 0;
        s[t] = v;
        sOrig[t] = v;
    }
    __syncthreads();
#pragma unroll
    for (int off = 1; off < 256; off <<= 1) {
        int tv = 0;
        if (t < 256 && t >= off) tv = s[t - off];
        __syncthreads();
        if (t < 256) s[t] += tv;
        __syncthreads();
    }
    int pref = s[blockIdx.x] - sOrig[blockIdx.x];
    int i = blockIdx.x * 512 + t;
    if (i < n) {
        int o = d_loc[i] + pref;
        d_off[i] = o;
        d_pos[i] = o;
        d_dinv[i] = rsqrtf(1.0f + (float)d_degi[i]);
    }
    if (blockIdx.x == 0 && t == 0) d_off[n] = e;
}

// ================= CSR fill =================
__global__ void k_fill(const int* __restrict__ src, const int* __restrict__ dst, int e) {
    int i = blockIdx.x * blockDim.x + threadIdx.x;
    if (i < e) {
        int d = dst[i];
        int p = atomicAdd(&d_pos[d], 1);
        d_csr[p] = src[i];
    }
}

// ================= GEMM1: g1 = x @ W1 (unscaled, fp16 out) =================
__global__ void k_gemm1(const float* __restrict__ x, const float* __restrict__ W, int n) {
    __shared__ float4 xs4[32 * 33];
    __shared__ float  ws[32][68];
    int tid = threadIdx.x;
    int tx = tid & 15, ty = tid >> 4;
    int nodeBase = blockIdx.x * 128;
    float acc[8][4] = {};

    for (int kc = 0; kc < F0; kc += 32) {
#pragma unroll
        for (int i = 0; i < 4; ++i) {
            int flat = i * 256 + tid;
            int row = flat >> 3;
            int c4  = flat & 7;
            int node = nodeBase + row;
            float4 v = make_float4(0.f, 0.f, 0.f, 0.f);
            if (node < n) v = __ldg((const float4*)(x + (size_t)node * F0 + kc + 4 * c4));
            int g = row >> 2, el = row & 3;
            const float vv[4] = {v.x, v.y, v.z, v.w};
#pragma unroll
            for (int j = 0; j < 4; ++j) {
                int k = 4 * c4 + j;
                float* p = (float*)&xs4[k * 33 + (g ^ ((k >> 2) & 7))];
                p[el] = vv[j];
            }
        }
#pragma unroll
        for (int i = 0; i < 2; ++i) {
            int flat = i * 256 + tid;
            int k = flat >> 4;
            int c4 = flat & 15;
            float4 w = __ldg((const float4*)(W + (size_t)(kc + k) * F1 + 4 * c4));
            *(float4*)&ws[k][4 * c4] = w;
        }
        __syncthreads();
#pragma unroll
        for (int k = 0; k < 32; ++k) {
            int swz = (k >> 2) & 7;
            float4 A0 = xs4[k * 33 + ((2 * ty) ^ swz)];
            float4 A1 = xs4[k * 33 + ((2 * ty + 1) ^ swz)];
            float4 B  = *(const float4*)&ws[k][4 * tx];
            float a[8] = {A0.x, A0.y, A0.z, A0.w, A1.x, A1.y, A1.z, A1.w};
            float b[4] = {B.x, B.y, B.z, B.w};
#pragma unroll
            for (int m = 0; m < 8; ++m)
#pragma unroll
                for (int q = 0; q < 4; ++q)
                    acc[m][q] += a[m] * b[q];
        }
        __syncthreads();
    }

#pragma unroll
    for (int m = 0; m < 8; ++m) {
        int node = nodeBase + 8 * ty + m;
        if (node < n) {
            __half2 p0 = __floats2half2_rn(acc[m][0], acc[m][1]);
            __half2 p1 = __floats2half2_rn(acc[m][2], acc[m][3]);
            uint2 u;
            u.x = *(unsigned*)&p0;
            u.y = *(unsigned*)&p1;
            ((uint2*)d_g1)[(size_t)node * 16 + tx] = u;
        }
    }
}

// ================= Gather layer1 (warp per node) =================
// h1[d] = relu(dinv[d]*(sum_s dinv[s]*g1[s] + dinv[d]*g1[d]) + b1)
// 32 lanes/node: lane owns one half2 word of the 128B row. 1 line per edge.
__device__ __forceinline__ float2 h2f(unsigned u) {
    return __half22float2(*(__half2*)&u);
}

__global__ void k_gather1(const float* __restrict__ b1, int n) {
    int node = (blockIdx.x * blockDim.x + threadIdx.x) >> 5;
    int lane = threadIdx.x & 31;
    if (node >= n) return;
    const unsigned* g1 = (const unsigned*)d_g1;  // 32 words per row
    float dv = __ldg(&d_dinv[node]);
    float2 acc;
    {
        float2 f = h2f(__ldg(&g1[(size_t)node * 32 + lane]));  // self loop
        acc.x = f.x * dv;
        acc.y = f.y * dv;
    }
    int beg = __ldg(&d_off[node]), end = __ldg(&d_off[node + 1]);
    int j = beg;
    for (; j + 4 <= end; j += 4) {
        int s0 = __ldg(&d_csr[j + 0]);
        int s1 = __ldg(&d_csr[j + 1]);
        int s2 = __ldg(&d_csr[j + 2]);
        int s3 = __ldg(&d_csr[j + 3]);
        float w0 = __ldg(&d_dinv[s0]);
        float w1 = __ldg(&d_dinv[s1]);
        float w2 = __ldg(&d_dinv[s2]);
        float w3 = __ldg(&d_dinv[s3]);
        unsigned u0 = __ldg(&g1[(size_t)s0 * 32 + lane]);
        unsigned u1 = __ldg(&g1[(size_t)s1 * 32 + lane]);
        unsigned u2 = __ldg(&g1[(size_t)s2 * 32 + lane]);
        unsigned u3 = __ldg(&g1[(size_t)s3 * 32 + lane]);
        float2 f0 = h2f(u0), f1 = h2f(u1), f2 = h2f(u2), f3 = h2f(u3);
        acc.x = fmaf(f0.x, w0, acc.x); acc.y = fmaf(f0.y, w0, acc.y);
        acc.x = fmaf(f1.x, w1, acc.x); acc.y = fmaf(f1.y, w1, acc.y);
        acc.x = fmaf(f2.x, w2, acc.x); acc.y = fmaf(f2.y, w2, acc.y);
        acc.x = fmaf(f3.x, w3, acc.x); acc.y = fmaf(f3.y, w3, acc.y);
    }
    for (; j < end; ++j) {
        int s = __ldg(&d_csr[j]);
        float w = __ldg(&d_dinv[s]);
        float2 f = h2f(__ldg(&g1[(size_t)s * 32 + lane]));
        acc.x = fmaf(f.x, w, acc.x);
        acc.y = fmaf(f.y, w, acc.y);
    }
    float2 bb = __ldg(&((const float2*)b1)[lane]);
    float2 h;
    h.x = fmaxf(fmaf(acc.x, dv, bb.x), 0.f);
    h.y = fmaxf(fmaf(acc.y, dv, bb.y), 0.f);
    ((float2*)d_h1)[(size_t)node * 32 + lane] = h;
}

// ================= GEMM2: g2 = (h1 @ W2) * dinv (fp16 out) =================
__global__ void k_gemm2(const float* __restrict__ W2, int n) {
    __shared__ float4 xs4[64 * 33];
    __shared__ float  ws[64][36];
    int tid = threadIdx.x;
    int tx = tid & 15, ty = tid >> 4;
    int nodeBase = blockIdx.x * 128;
    float acc[8][2] = {};

#pragma unroll
    for (int i = 0; i < 8; ++i) {
        int flat = i * 256 + tid;
        int row = flat >> 4;
        int c4  = flat & 15;
        int node = nodeBase + row;
        float4 v = make_float4(0.f, 0.f, 0.f, 0.f);
        if (node < n) v = __ldg((const float4*)(d_h1 + (size_t)node * F1 + 4 * c4));
        int g = row >> 2, el = row & 3;
        const float vv[4] = {v.x, v.y, v.z, v.w};
#pragma unroll
        for (int j = 0; j < 4; ++j) {
            int k = 4 * c4 + j;
            float* p = (float*)&xs4[k * 33 + (g ^ ((k >> 2) & 7))];
            p[el] = vv[j];
        }
    }
#pragma unroll
    for (int i = 0; i < 2; ++i) {
        int flat = i * 256 + tid;
        int k = flat >> 3;
        int c4 = flat & 7;
        float4 w = __ldg((const float4*)(W2 + (size_t)k * F2 + 4 * c4));
        *(float4*)&ws[k][4 * c4] = w;
    }
    __syncthreads();

#pragma unroll
    for (int k = 0; k < 64; ++k) {
        int swz = (k >> 2) & 7;
        float4 A0 = xs4[k * 33 + ((2 * ty) ^ swz)];
        float4 A1 = xs4[k * 33 + ((2 * ty + 1) ^ swz)];
        float b0 = ws[k][2 * tx + 0];
        float b1 = ws[k][2 * tx + 1];
        float a[8] = {A0.x, A0.y, A0.z, A0.w, A1.x, A1.y, A1.z, A1.w};
#pragma unroll
        for (int m = 0; m < 8; ++m) {
            acc[m][0] += a[m] * b0;
            acc[m][1] += a[m] * b1;
        }
    }

#pragma unroll
    for (int m = 0; m < 8; ++m) {
        int node = nodeBase + 8 * ty + m;
        if (node < n) {
            float dv = d_dinv[node];
            __half2 p = __floats2half2_rn(acc[m][0] * dv, acc[m][1] * dv);
            ((__half2*)d_g2)[(size_t)node * 16 + tx] = p;
        }
    }
}

// ================= Gather layer2 (warp per node, half-warp per edge) ====
// out[d] = dinv[d]*(sum_s g2[s] + g2[d]) + b2 ; g2 pre-scaled by dinv[s].
// Row = 64B = 16 half2. Lanes 0-15 handle even-offset edges, 16-31 odd.
__global__ void k_gather2(const float* __restrict__ b2, float* __restrict__ out, int n) {
    int node = (blockIdx.x * blockDim.x + threadIdx.x) >> 5;
    int lane = threadIdx.x & 31;
    if (node >= n) return;
    int hw = lane >> 4, fl = lane & 15;
    const unsigned* g2 = (const unsigned*)d_g2;  // 16 words per row
    float2 acc = make_float2(0.f, 0.f);
    if (hw == 0) {
        float2 f = h2f(__ldg(&g2[(size_t)node * 16 + fl]));  // self loop
        acc.x = f.x;
        acc.y = f.y;
    }
    int beg = __ldg(&d_off[node]), end = __ldg(&d_off[node + 1]);
    int j = beg;
    for (; j + 4 <= end; j += 4) {
        int s0 = __ldg(&d_csr[j + hw]);
        int s1 = __ldg(&d_csr[j + 2 + hw]);
        unsigned u0 = __ldg(&g2[(size_t)s0 * 16 + fl]);
        unsigned u1 = __ldg(&g2[(size_t)s1 * 16 + fl]);
        float2 f0 = h2f(u0), f1 = h2f(u1);
        acc.x += f0.x + f1.x;
        acc.y += f0.y + f1.y;
    }
    for (; j + 2 <= end; j += 2) {
        int s = __ldg(&d_csr[j + hw]);
        float2 f = h2f(__ldg(&g2[(size_t)s * 16 + fl]));
        acc.x += f.x;
        acc.y += f.y;
    }
    if (j < end && hw == 0) {
        int s = __ldg(&d_csr[j]);
        float2 f = h2f(__ldg(&g2[(size_t)s * 16 + fl]));
        acc.x += f.x;
        acc.y += f.y;
    }
    acc.x += __shfl_xor_sync(0xffffffffu, acc.x, 16);
    acc.y += __shfl_xor_sync(0xffffffffu, acc.y, 16);
    if (hw == 0) {
        float dv = __ldg(&d_dinv[node]);
        float2 bb = __ldg(&((const float2*)b2)[fl]);
        float2 o;
        o.x = fmaf(acc.x, dv, bb.x);
        o.y = fmaf(acc.y, dv, bb.y);
        ((float2*)out)[(size_t)node * 16 + fl] = o;
    }
}

extern "C" void kernel_launch(void* const* d_in, const int* in_sizes, int n_in,
                              void* d_out, int out_size) {
    const float* x  = (const float*)d_in[0];
    const int*   ei = (const int*)d_in[1];
    const float* W1 = (const float*)d_in[2];
    const float* b1 = (const float*)d_in[3];
    const float* W2 = (const float*)d_in[4];
    const float* b2 = (const float*)d_in[5];
    float* out = (float*)d_out;

    int n = in_sizes[0] / F0;   // 100000
    int e = in_sizes[1] / 2;    // 1600000
    const int* src = ei;
    const int* dst = ei + e;
    int nb = (n + 511) / 512;   // 196

    // Fork: GEMM1 on side stream (independent of graph structure).
    cudaEventRecord(g_ss.fork, 0);
    cudaStreamWaitEvent(g_ss.s, g_ss.fork, 0);
    k_gemm1<<<(n + 127) / 128, 256, 0, g_ss.s>>>(x, W1, n);

    // CSR build on main stream.
    k_zero<<<(n + 255) / 256, 256>>>(n);
    k_count<<<(e + 255) / 256, 256>>>(dst, e);
    k_scan1<<<nb, 512>>>(n);
    k_scan2f<<<nb, 512>>>(n, nb, e);
    k_fill<<<(e + 255) / 256, 256>>>(src, dst, e);

    cudaEventRecord(g_ss.join, g_ss.s);
    cudaStreamWaitEvent(0, g_ss.join, 0);

    // warp per node: 8 nodes per 256-thread block
    k_gather1<<<(n + 7) / 8, 256>>>(b1, n);
    k_gemm2<<<(n + 127) / 128, 256>>>(W2, n);
    k_gather2<<<(n + 7) / 8, 256>>>(b2, out, n);
}

// round 7
// speedup vs baseline: 1.3426x; 1.1082x over previous
#include <cuda_runtime.h>
#include <cstdint>

#define NODES 100000
#define EMAX  1600000
#define F0 128
#define F1 64
#define F2 32
#define NB_SCAN 196          // ceil(100000/512)

// ---- scratch (static device globals: allocation-free) ----
__device__ int    d_degi[NODES];
__device__ unsigned long long d_scanstate[NB_SCAN];  // (sum<<2)|flag: 0=inv,1=partial,2=prefix
__device__ int    d_ticket;
__device__ int    d_off[NODES + 1];
__device__ int    d_pos[NODES];
__device__ int    d_csr[EMAX];
__device__ float  d_dinv[NODES];
__device__ float  d_g1[(size_t)NODES * F1];   // (x@W1)*dinv[src], fp32
__device__ float  d_h1[(size_t)NODES * F1];   // relu layer-1 output
__device__ float  d_g2[(size_t)NODES * F2];   // (h1@W2)*dinv[src]

struct SideStream {
    cudaStream_t s;
    cudaEvent_t evA, evB;
    SideStream() {
        cudaStreamCreateWithFlags(&s, cudaStreamNonBlocking);
        cudaEventCreateWithFlags(&evA, cudaEventDisableTiming);
        cudaEventCreateWithFlags(&evB, cudaEventDisableTiming);
    }
};
static SideStream g_ss;

// ================= zero degree + scan state =================
__global__ void k_zero(int n, int nb) {
    int i = blockIdx.x * blockDim.x + threadIdx.x;
    if (i < n) d_degi[i] = 0;
    if (i < nb) d_scanstate[i] = 0ULL;
    if (i == 0) d_ticket = 0;
}

// ================= degree histogram (4 edges/thread) =================
__global__ void k_count4(const int* __restrict__ dst, int e) {
    int i = (blockIdx.x * blockDim.x + threadIdx.x) * 4;
    if (i + 4 <= e) {
        int4 d = *(const int4*)(dst + i);
        atomicAdd(&d_degi[d.x], 1);
        atomicAdd(&d_degi[d.y], 1);
        atomicAdd(&d_degi[d.z], 1);
        atomicAdd(&d_degi[d.w], 1);
    } else {
        for (; i < e; ++i) atomicAdd(&d_degi[dst[i]], 1);
    }
}

// ================= single-pass scan: decoupled lookback =================
__global__ void k_scanLB(int n, int e) {
    __shared__ int sbid, spref;
    __shared__ int warpsum[16];
    int tid = threadIdx.x, lane = tid & 31, w = tid >> 5;
    if (tid == 0) sbid = atomicAdd(&d_ticket, 1);
    __syncthreads();
    int bid = sbid;
    int i = bid * 512 + tid;
    int deg = (i < n) ? d_degi[i] : 0;

    // warp-shuffle inclusive scan
    int incl = deg;
#pragma unroll
    for (int d = 1; d < 32; d <<= 1) {
        int t = __shfl_up_sync(0xffffffffu, incl, d);
        if (lane >= d) incl += t;
    }
    if (lane == 31) warpsum[w] = incl;
    __syncthreads();
    if (w == 0) {
        int s = (lane < 16) ? warpsum[lane] : 0;
#pragma unroll
        for (int d = 1; d < 16; d <<= 1) {
            int t = __shfl_up_sync(0xffffffffu, s, d);
            if (lane >= d) s += t;
        }
        if (lane < 16) warpsum[lane] = s;
    }
    __syncthreads();
    int total = warpsum[15];
    incl += (w > 0) ? warpsum[w - 1] : 0;

    // publish partial (block 0 publishes prefix directly)
    if (tid == 0)
        atomicExch(&d_scanstate[bid],
                   ((unsigned long long)total << 2) | (bid == 0 ? 2ULL : 1ULL));

    // warp-wide lookback
    if (w == 0) {
        int pref = 0;
        if (bid > 0) {
            int j = bid - 1;
            while (true) {
                int idx = j - (int)lane;
                unsigned long long st;
                if (idx >= 0) {
                    do { st = atomicAdd(&d_scanstate[idx], 0ULL); } while ((st & 3ULL) == 0ULL);
                } else {
                    st = 2ULL;  // virtual prefix 0
                }
                unsigned pmask = __ballot_sync(0xffffffffu, (st & 3ULL) == 2ULL);
                int val = (int)(st >> 2);
                int contrib;
                if (pmask) {
                    int k = __ffs(pmask) - 1;  // nearest prefix
                    contrib = (lane <= k) ? val : 0;
                } else {
                    contrib = val;
                }
#pragma unroll
                for (int o = 16; o; o >>= 1) contrib += __shfl_xor_sync(0xffffffffu, contrib, o);
                pref += contrib;
                if (pmask) break;
                j -= 32;
            }
            if (lane == 0)
                atomicExch(&d_scanstate[bid],
                           ((unsigned long long)(pref + total) << 2) | 2ULL);
        }
        if (lane == 0) spref = pref;
    }
    __syncthreads();

    int ex = spref + incl - deg;  // exclusive offset
    if (i < n) {
        d_off[i] = ex;
        d_pos[i] = ex;
        d_dinv[i] = rsqrtf(1.0f + (float)deg);  // +1 self-loop
    }
    if (i == n - 1) d_off[n] = e;
}

// ================= CSR fill (4 edges/thread) =================
__global__ void k_fill4(const int* __restrict__ src, const int* __restrict__ dst, int e) {
    int i = (blockIdx.x * blockDim.x + threadIdx.x) * 4;
    if (i + 4 <= e) {
        int4 s = *(const int4*)(src + i);
        int4 d = *(const int4*)(dst + i);
        int p0 = atomicAdd(&d_pos[d.x], 1); d_csr[p0] = s.x;
        int p1 = atomicAdd(&d_pos[d.y], 1); d_csr[p1] = s.y;
        int p2 = atomicAdd(&d_pos[d.z], 1); d_csr[p2] = s.z;
        int p3 = atomicAdd(&d_pos[d.w], 1); d_csr[p3] = s.w;
    } else {
        for (; i < e; ++i) {
            int d = dst[i];
            int p = atomicAdd(&d_pos[d], 1);
            d_csr[p] = src[i];
        }
    }
}

// ================= GEMM1: g1 = (x @ W1) * dinv (prescaled, fp32) ==========
// 128 nodes x 64 cols / block, 256 threads, 8x4 register tile, swizzled LDS.128
__global__ void k_gemm1(const float* __restrict__ x, const float* __restrict__ W, int n) {
    __shared__ float4 xs4[32 * 33];
    __shared__ float  ws[32][68];
    int tid = threadIdx.x;
    int tx = tid & 15, ty = tid >> 4;
    int nodeBase = blockIdx.x * 128;
    float acc[8][4] = {};

    for (int kc = 0; kc < F0; kc += 32) {
#pragma unroll
        for (int i = 0; i < 4; ++i) {
            int flat = i * 256 + tid;
            int row = flat >> 3;
            int c4  = flat & 7;
            int node = nodeBase + row;
            float4 v = make_float4(0.f, 0.f, 0.f, 0.f);
            if (node < n) v = __ldg((const float4*)(x + (size_t)node * F0 + kc + 4 * c4));
            int g = row >> 2, el = row & 3;
            const float vv[4] = {v.x, v.y, v.z, v.w};
#pragma unroll
            for (int j = 0; j < 4; ++j) {
                int k = 4 * c4 + j;
                float* p = (float*)&xs4[k * 33 + (g ^ ((k >> 2) & 7))];
                p[el] = vv[j];
            }
        }
#pragma unroll
        for (int i = 0; i < 2; ++i) {
            int flat = i * 256 + tid;
            int k = flat >> 4;
            int c4 = flat & 15;
            float4 w = __ldg((const float4*)(W + (size_t)(kc + k) * F1 + 4 * c4));
            *(float4*)&ws[k][4 * c4] = w;
        }
        __syncthreads();
#pragma unroll
        for (int k = 0; k < 32; ++k) {
            int swz = (k >> 2) & 7;
            float4 A0 = xs4[k * 33 + ((2 * ty) ^ swz)];
            float4 A1 = xs4[k * 33 + ((2 * ty + 1) ^ swz)];
            float4 B  = *(const float4*)&ws[k][4 * tx];
            float a[8] = {A0.x, A0.y, A0.z, A0.w, A1.x, A1.y, A1.z, A1.w};
            float b[4] = {B.x, B.y, B.z, B.w};
#pragma unroll
            for (int m = 0; m < 8; ++m)
#pragma unroll
                for (int q = 0; q < 4; ++q)
                    acc[m][q] += a[m] * b[q];
        }
        __syncthreads();
    }

#pragma unroll
    for (int m = 0; m < 8; ++m) {
        int node = nodeBase + 8 * ty + m;
        if (node < n) {
            float dv = __ldg(&d_dinv[node]);
            float4 o = make_float4(acc[m][0] * dv, acc[m][1] * dv,
                                   acc[m][2] * dv, acc[m][3] * dv);
            *(float4*)(d_g1 + (size_t)node * F1 + 4 * tx) = o;
        }
    }
}

// ================= Gather layer1 =================
// h1[d] = relu(dinv[d]*(sum_s g1[s] + g1[d]) + b1) ; g1 prescaled by dinv[s].
// 16 lanes/node, float4 per lane, unrolled x4.
__global__ void k_gather1(const float* __restrict__ b1, int n) {
    int node = (blockIdx.x * blockDim.x + threadIdx.x) >> 4;
    int lane = threadIdx.x & 15;
    if (node >= n) return;
    const float4* g1 = (const float4*)d_g1;  // 16 float4 per row
    float4 acc = __ldg(&g1[(size_t)node * 16 + lane]);  // self loop
    int beg = __ldg(&d_off[node]), end = __ldg(&d_off[node + 1]);
    int j = beg;
    for (; j + 4 <= end; j += 4) {
        int s0 = __ldg(&d_csr[j + 0]);
        int s1 = __ldg(&d_csr[j + 1]);
        int s2 = __ldg(&d_csr[j + 2]);
        int s3 = __ldg(&d_csr[j + 3]);
        float4 v0 = __ldg(&g1[(size_t)s0 * 16 + lane]);
        float4 v1 = __ldg(&g1[(size_t)s1 * 16 + lane]);
        float4 v2 = __ldg(&g1[(size_t)s2 * 16 + lane]);
        float4 v3 = __ldg(&g1[(size_t)s3 * 16 + lane]);
        acc.x += (v0.x + v1.x) + (v2.x + v3.x);
        acc.y += (v0.y + v1.y) + (v2.y + v3.y);
        acc.z += (v0.z + v1.z) + (v2.z + v3.z);
        acc.w += (v0.w + v1.w) + (v2.w + v3.w);
    }
    for (; j < end; ++j) {
        int s = __ldg(&d_csr[j]);
        float4 v = __ldg(&g1[(size_t)s * 16 + lane]);
        acc.x += v.x; acc.y += v.y; acc.z += v.z; acc.w += v.w;
    }
    float dv = __ldg(&d_dinv[node]);
    float4 bb = __ldg(&((const float4*)b1)[lane]);
    float4 h;
    h.x = fmaxf(fmaf(acc.x, dv, bb.x), 0.f);
    h.y = fmaxf(fmaf(acc.y, dv, bb.y), 0.f);
    h.z = fmaxf(fmaf(acc.z, dv, bb.z), 0.f);
    h.w = fmaxf(fmaf(acc.w, dv, bb.w), 0.f);
    ((float4*)d_h1)[(size_t)node * 16 + lane] = h;
}

// ================= GEMM2: g2 = (h1 @ W2) * dinv (fp32) =================
__global__ void k_gemm2(const float* __restrict__ W2, int n) {
    __shared__ float4 xs4[64 * 33];
    __shared__ float  ws[64][36];
    int tid = threadIdx.x;
    int tx = tid & 15, ty = tid >> 4;
    int nodeBase = blockIdx.x * 128;
    float acc[8][2] = {};

#pragma unroll
    for (int i = 0; i < 8; ++i) {
        int flat = i * 256 + tid;
        int row = flat >> 4;
        int c4  = flat & 15;
        int node = nodeBase + row;
        float4 v = make_float4(0.f, 0.f, 0.f, 0.f);
        if (node < n) v = __ldg((const float4*)(d_h1 + (size_t)node * F1 + 4 * c4));
        int g = row >> 2, el = row & 3;
        const float vv[4] = {v.x, v.y, v.z, v.w};
#pragma unroll
        for (int j = 0; j < 4; ++j) {
            int k = 4 * c4 + j;
            float* p = (float*)&xs4[k * 33 + (g ^ ((k >> 2) & 7))];
            p[el] = vv[j];
        }
    }
#pragma unroll
    for (int i = 0; i < 2; ++i) {
        int flat = i * 256 + tid;
        int k = flat >> 3;
        int c4 = flat & 7;
        float4 w = __ldg((const float4*)(W2 + (size_t)k * F2 + 4 * c4));
        *(float4*)&ws[k][4 * c4] = w;
    }
    __syncthreads();

#pragma unroll
    for (int k = 0; k < 64; ++k) {
        int swz = (k >> 2) & 7;
        float4 A0 = xs4[k * 33 + ((2 * ty) ^ swz)];
        float4 A1 = xs4[k * 33 + ((2 * ty + 1) ^ swz)];
        float b0 = ws[k][2 * tx + 0];
        float b1 = ws[k][2 * tx + 1];
        float a[8] = {A0.x, A0.y, A0.z, A0.w, A1.x, A1.y, A1.z, A1.w};
#pragma unroll
        for (int m = 0; m < 8; ++m) {
            acc[m][0] += a[m] * b0;
            acc[m][1] += a[m] * b1;
        }
    }

#pragma unroll
    for (int m = 0; m < 8; ++m) {
        int node = nodeBase + 8 * ty + m;
        if (node < n) {
            float dv = __ldg(&d_dinv[node]);
            float2 o = make_float2(acc[m][0] * dv, acc[m][1] * dv);
            *(float2*)(d_g2 + (size_t)node * F2 + 2 * tx) = o;
        }
    }
}

// ================= Gather layer2 =================
// out[d] = dinv[d]*(sum_s g2[s] + g2[d]) + b2 ; g2 prescaled by dinv[s].
// 16 lanes/node, float2 per lane (128B row = 1 wavefront/edge), unrolled x4.
__global__ void k_gather2(const float* __restrict__ b2, float* __restrict__ out, int n) {
    int node = (blockIdx.x * blockDim.x + threadIdx.x) >> 4;
    int lane = threadIdx.x & 15;
    if (node >= n) return;
    const float2* g2 = (const float2*)d_g2;  // 16 float2 per row
    float2 acc = __ldg(&g2[(size_t)node * 16 + lane]);  // self loop
    int beg = __ldg(&d_off[node]), end = __ldg(&d_off[node + 1]);
    int j = beg;
    for (; j + 4 <= end; j += 4) {
        int s0 = __ldg(&d_csr[j + 0]);
        int s1 = __ldg(&d_csr[j + 1]);
        int s2 = __ldg(&d_csr[j + 2]);
        int s3 = __ldg(&d_csr[j + 3]);
        float2 v0 = __ldg(&g2[(size_t)s0 * 16 + lane]);
        float2 v1 = __ldg(&g2[(size_t)s1 * 16 + lane]);
        float2 v2 = __ldg(&g2[(size_t)s2 * 16 + lane]);
        float2 v3 = __ldg(&g2[(size_t)s3 * 16 + lane]);
        acc.x += (v0.x + v1.x) + (v2.x + v3.x);
        acc.y += (v0.y + v1.y) + (v2.y + v3.y);
    }
    for (; j < end; ++j) {
        int s = __ldg(&d_csr[j]);
        float2 v = __ldg(&g2[(size_t)s * 16 + lane]);
        acc.x += v.x;
        acc.y += v.y;
    }
    float dv = __ldg(&d_dinv[node]);
    float2 bb = __ldg(&((const float2*)b2)[lane]);
    float2 o;
    o.x = fmaf(acc.x, dv, bb.x);
    o.y = fmaf(acc.y, dv, bb.y);
    ((float2*)out)[(size_t)node * 16 + lane] = o;
}

extern "C" void kernel_launch(void* const* d_in, const int* in_sizes, int n_in,
                              void* d_out, int out_size) {
    const float* x  = (const float*)d_in[0];
    const int*   ei = (const int*)d_in[1];
    const float* W1 = (const float*)d_in[2];
    const float* b1 = (const float*)d_in[3];
    const float* W2 = (const float*)d_in[4];
    const float* b2 = (const float*)d_in[5];
    float* out = (float*)d_out;

    int n = in_sizes[0] / F0;   // 100000
    int e = in_sizes[1] / 2;    // 1600000
    const int* src = ei;
    const int* dst = ei + e;
    int nb = (n + 511) / 512;   // 196
    int eg4 = (e / 4 + 255) / 256 + 1;  // grid for 4-edges/thread kernels

    // CSR degree + offsets on main stream
    k_zero<<<(n + 255) / 256, 256>>>(n, nb);
    k_count4<<<eg4, 256>>>(dst, e);
    k_scanLB<<<nb, 512>>>(n, e);

    // Fork: gemm1 (needs dinv only) overlaps fill (atomic-bound).
    cudaEventRecord(g_ss.evA, 0);
    cudaStreamWaitEvent(g_ss.s, g_ss.evA, 0);
    k_gemm1<<<(n + 127) / 128, 256, 0, g_ss.s>>>(x, W1, n);
    cudaEventRecord(g_ss.evB, g_ss.s);

    k_fill4<<<eg4, 256>>>(src, dst, e);

    cudaStreamWaitEvent(0, g_ss.evB, 0);

    k_gather1<<<(n + 15) / 16, 256>>>(b1, n);
    k_gemm2<<<(n + 127) / 128, 256>>>(W2, n);
    k_gather2<<<(n + 15) / 16, 256>>>(b2, out, n);
}